// round 5
// baseline (speedup 1.0000x reference)
#include <cuda_runtime.h>
#include <cstdint>

#define MQ   32000
#define HN   32
#define CC   64
#define KK   15
#define COUTN 120

typedef unsigned long long ull;

// scratch
__device__ float g_mod[(size_t)MQ * COUTN];    // sigmoid(mod), (M,120)
__device__ ull   g_geo[(size_t)MQ * HN];       // hi32: infl bits, lo32: (k<<26)|(ind<<6)

// ---------------- f32x2 packed helpers (sm_103a) ----------------
__device__ __forceinline__ ull pack2(float a, float b) {
    ull r; asm("mov.b64 %0,{%1,%2};" : "=l"(r) : "f"(a), "f"(b)); return r;
}
__device__ __forceinline__ void unpack2(ull v, float& a, float& b) {
    asm("mov.b64 {%0,%1},%2;" : "=f"(a), "=f"(b) : "l"(v));
}
__device__ __forceinline__ ull fma2(ull a, ull b, ull c) {
    ull d; asm("fma.rn.f32x2 %0,%1,%2,%3;" : "=l"(d) : "l"(a), "l"(b), "l"(c)); return d;
}
__device__ __forceinline__ ull mul2(ull a, ull b) {
    ull d; asm("mul.rn.f32x2 %0,%1,%2;" : "=l"(d) : "l"(a), "l"(b)); return d;
}
__device__ __forceinline__ ull add2(ull a, ull b) {
    ull d; asm("add.rn.f32x2 %0,%1,%2;" : "=l"(d) : "l"(a), "l"(b)); return d;
}

// ---------------------------------------------------------------------------
// geom_kernel: per-neighbor argmin over 15 kernel points + linear influence.
// Warp per query, lane per neighbor. No g_mod dependency -> runs concurrent
// with mlp on a side stream. Writes packed (infl, k|ind) to g_geo.
// ---------------------------------------------------------------------------
__global__ __launch_bounds__(256) void geom_kernel(
    const float* __restrict__ q_pts,
    const float* __restrict__ s_pts,
    const int*   __restrict__ nidx,
    const float* __restrict__ kpts)
{
    __shared__ float skp[45];
    const int tid  = threadIdx.x;
    const int wid  = tid >> 5;
    const int lane = tid & 31;
    const int m    = blockIdx.x * 8 + wid;

    if (tid < 45) skp[tid] = kpts[tid];
    __syncthreads();

    const int ind = nidx[m * HN + lane];
    const float qx = __ldg(&q_pts[m*3+0]), qy = __ldg(&q_pts[m*3+1]), qz = __ldg(&q_pts[m*3+2]);
    const float nx = __ldg(&s_pts[ind*3+0]) - qx;
    const float ny = __ldg(&s_pts[ind*3+1]) - qy;
    const float nz = __ldg(&s_pts[ind*3+2]) - qz;

    float best = 3.4e38f; int bk = 0;
#pragma unroll
    for (int k = 0; k < 15; k++) {
        float dx = nx - skp[k*3+0];
        float dy = ny - skp[k*3+1];
        float dz = nz - skp[k*3+2];
        float d2 = fmaf(dx, dx, fmaf(dy, dy, dz*dz));
        if (d2 < best) { best = d2; bk = k; }   // strict <: first-min like argmin
    }
    const float infl = fmaxf(0.f, 1.f - sqrtf(best));
    const unsigned pk = ((unsigned)bk << 26) | ((unsigned)ind << 6);
    g_geo[(size_t)m * HN + lane] = ((ull)__float_as_uint(infl) << 32) | pk;
}

// ---------------------------------------------------------------------------
// mlp_kernel: per-point MLP, f32x2 FMAs, two warps per 32-row group.
// 256 threads/block -> 128 rows/block, 250 blocks.
// smem (ull): w1t 2048 + w2p 3840 + b1 32 + hx 128*33 = 10144 (81152 B)
// ---------------------------------------------------------------------------
__global__ __launch_bounds__(256, 2) void mlp_kernel(
    const float* __restrict__ X,
    const float* __restrict__ w1,
    const float* __restrict__ b1,
    const float* __restrict__ w2)
{
    extern __shared__ ull shu[];
    ull* w1t = shu;              // [c2*64 + j]  = (w1[2c2][j],  w1[2c2+1][j])
    ull* w2p = shu + 2048;       // [j2*120 + o] = (w2[2j2][o],  w2[2j2+1][o])
    ull* b1u = shu + 5888;       // 32
    ull* hx  = shu + 5920;       // 128 rows * stride 33

    const int tid  = threadIdx.x;
    const int wid  = tid >> 5;
    const int lane = tid & 31;
    const int half = wid & 1;
    const int rloc = (wid >> 1) * 32 + lane;        // 0..127
    const int r    = blockIdx.x * 128 + rloc;

    for (int i = tid; i < 2048; i += 256) {
        int c2 = i >> 6, j = i & 63;
        w1t[i] = pack2(w1[(2*c2)*64 + j], w1[(2*c2+1)*64 + j]);
    }
    for (int i = tid; i < 3840; i += 256) {
        int j2 = i / 120, o = i - j2 * 120;
        w2p[i] = pack2(w2[(2*j2)*120 + o], w2[(2*j2+1)*120 + o]);
    }
    if (tid < 32) b1u[tid] = ((const ull*)b1)[tid];
    __syncthreads();

    const float* b1f = reinterpret_cast<const float*>(b1u);

    ull xr[32];
    {
        const ulonglong2* xv = reinterpret_cast<const ulonglong2*>(X + (size_t)r * 64);
#pragma unroll
        for (int i = 0; i < 16; i++) { ulonglong2 v = xv[i]; xr[2*i] = v.x; xr[2*i+1] = v.y; }
    }

    // layer 1: warp computes h[j] for j in [half*32, half*32+32)
    const int jbase = half * 32;
    for (int jj = 0; jj < 32; jj += 4) {
        const int j = jbase + jj;
        ull a0 = 0, a1 = 0, a2 = 0, a3 = 0;
#pragma unroll
        for (int c2 = 0; c2 < 32; c2++) {
            ulonglong2 wA = *reinterpret_cast<const ulonglong2*>(&w1t[c2*64 + j]);
            ulonglong2 wB = *reinterpret_cast<const ulonglong2*>(&w1t[c2*64 + j + 2]);
            ull x = xr[c2];
            a0 = fma2(x, wA.x, a0);
            a1 = fma2(x, wA.y, a1);
            a2 = fma2(x, wB.x, a2);
            a3 = fma2(x, wB.y, a3);
        }
        float h[4]; ull aa[4] = {a0, a1, a2, a3};
#pragma unroll
        for (int t = 0; t < 4; t++) {
            float lo, hi; unpack2(aa[t], lo, hi);
            float v = lo + hi + b1f[j + t];
            h[t] = (v >= 0.f) ? v : 0.1f * v;
        }
        hx[rloc * 33 + (j >> 1)]     = pack2(h[0], h[1]);
        hx[rloc * 33 + (j >> 1) + 1] = pack2(h[2], h[3]);
    }
    __syncthreads();

    ull hr[32];
#pragma unroll
    for (int j2 = 0; j2 < 32; j2++) hr[j2] = hx[rloc * 33 + j2];

    // layer 2: warp computes o in [half*60, half*60+60)
    float* op = g_mod + (size_t)r * COUTN;
    const int obase = half * 60;
    for (int oo = 0; oo < 60; oo += 4) {
        const int o = obase + oo;
        ull a0 = 0, a1 = 0, a2 = 0, a3 = 0;
#pragma unroll
        for (int j2 = 0; j2 < 32; j2++) {
            ulonglong2 wA = *reinterpret_cast<const ulonglong2*>(&w2p[j2*120 + o]);
            ulonglong2 wB = *reinterpret_cast<const ulonglong2*>(&w2p[j2*120 + o + 2]);
            ull h = hr[j2];
            a0 = fma2(h, wA.x, a0);
            a1 = fma2(h, wA.y, a1);
            a2 = fma2(h, wB.x, a2);
            a3 = fma2(h, wB.y, a3);
        }
        ull aa[4] = {a0, a1, a2, a3};
        float4 v; float* vp = &v.x;
#pragma unroll
        for (int t = 0; t < 4; t++) {
            float lo, hi; unpack2(aa[t], lo, hi);
            float s = lo + hi;
            vp[t] = 1.f / (1.f + __expf(-s));
        }
        *reinterpret_cast<float4*>(op + o) = v;
    }
}

// ---------------------------------------------------------------------------
// accum_kernel: gather-weighted reduction using precomputed geometry.
// Warp per query; half-warp g handles neighbors 2t+g; lane owns 4 channels.
// ---------------------------------------------------------------------------
__global__ __launch_bounds__(256) void accum_kernel(
    const float* __restrict__ s_feats,
    const float* __restrict__ Wg,
    float* __restrict__ out)
{
    __shared__ float sW[15 * 72];    // padded stride 72
    __shared__ float smod[8][120];
    __shared__ ull   sgeo[8][32];

    const int tid  = threadIdx.x;
    const int wid  = tid >> 5;
    const int lane = tid & 31;
    const int m    = blockIdx.x * 8 + wid;

    for (int i = tid; i < 960; i += 256) sW[(i >> 6) * 72 + (i & 63)] = Wg[i];
    for (int i = lane; i < 120; i += 32) smod[wid][i] = g_mod[(size_t)m * 120 + i];
    sgeo[wid][lane] = g_geo[(size_t)m * HN + lane];
    __syncthreads();

    const int g  = lane >> 4;
    const int cl = (lane & 15) << 2;
    ull acc0 = 0, acc1 = 0;
#pragma unroll
    for (int t = 0; t < 16; t++) {
        const ull      geo = sgeo[wid][2 * t + g];
        const float    s   = __uint_as_float((unsigned)(geo >> 32));
        const unsigned pkh = (unsigned)geo;
        const int      k   = pkh >> 26;
        const int      row = pkh & 0x03FFFFFF;
        const ulonglong2 f = *reinterpret_cast<const ulonglong2*>(s_feats + row + cl);
        const ulonglong2 w = *reinterpret_cast<const ulonglong2*>(&sW[k * 72 + cl]);
        const float sc = smod[wid][(k << 3) + (cl >> 3)] * s;
        const ull scp = pack2(sc, sc);
        acc0 = fma2(f.x, mul2(w.x, scp), acc0);
        acc1 = fma2(f.y, mul2(w.y, scp), acc1);
    }
    const unsigned FULL = 0xffffffffu;
    acc0 = add2(acc0, __shfl_xor_sync(FULL, acc0, 16));
    acc1 = add2(acc1, __shfl_xor_sync(FULL, acc1, 16));
    if (g == 0) {
        ulonglong2 v; v.x = acc0; v.y = acc1;
        *reinterpret_cast<ulonglong2*>(out + (size_t)m * 64 + cl) = v;
    }
}

// ---------------------------------------------------------------------------
extern "C" void kernel_launch(void* const* d_in, const int* in_sizes, int n_in,
                              void* d_out, int out_size)
{
    const float* q_pts   = (const float*)d_in[0];
    const float* s_pts   = (const float*)d_in[1];
    const float* s_feats = (const float*)d_in[2];
    const int*   nidx    = (const int*)  d_in[3];
    const float* kpts    = (const float*)d_in[4];
    const float* W       = (const float*)d_in[5];
    const float* w1      = (const float*)d_in[6];
    const float* b1      = (const float*)d_in[7];
    const float* w2      = (const float*)d_in[8];
    float* out = (float*)d_out;

    static cudaStream_t s2 = nullptr;
    static cudaEvent_t ev0, evg;
    const int smem = 10144 * 8;  // 81152 B
    if (!s2) {
        cudaStreamCreateWithFlags(&s2, cudaStreamNonBlocking);
        cudaEventCreateWithFlags(&ev0, cudaEventDisableTiming);
        cudaEventCreateWithFlags(&evg, cudaEventDisableTiming);
        cudaFuncSetAttribute(mlp_kernel, cudaFuncAttributeMaxDynamicSharedMemorySize, smem);
    }

    // fork: geometry on side stream, concurrent with mlp on default stream
    cudaEventRecord(ev0, 0);
    cudaStreamWaitEvent(s2, ev0, 0);
    geom_kernel<<<MQ / 8, 256, 0, s2>>>(q_pts, s_pts, nidx, kpts);
    cudaEventRecord(evg, s2);

    mlp_kernel<<<250, 256, smem>>>(s_feats, w1, b1, w2);

    // join: accumulation needs both g_mod (default stream) and g_geo (s2)
    cudaStreamWaitEvent(0, evg, 0);
    accum_kernel<<<MQ / 8, 256>>>(s_feats, W, out);
}

// round 6
// speedup vs baseline: 1.1700x; 1.1700x over previous
#include <cuda_runtime.h>
#include <cstdint>

#define MQ   32000
#define HN   32
#define CC   64
#define KK   15
#define COUTN 120

typedef unsigned long long ull;

// scratch
__device__ float  g_mod[(size_t)MQ * COUTN];   // sigmoid(mod), (M,120)
__device__ float4 g_pts4[MQ];                   // padded s_pts

// ---------------- f32x2 packed helpers (sm_103a) ----------------
__device__ __forceinline__ ull pack2(float a, float b) {
    ull r; asm("mov.b64 %0,{%1,%2};" : "=l"(r) : "f"(a), "f"(b)); return r;
}
__device__ __forceinline__ void unpack2(ull v, float& a, float& b) {
    asm("mov.b64 {%0,%1},%2;" : "=f"(a), "=f"(b) : "l"(v));
}
__device__ __forceinline__ ull fma2(ull a, ull b, ull c) {
    ull d; asm("fma.rn.f32x2 %0,%1,%2,%3;" : "=l"(d) : "l"(a), "l"(b), "l"(c)); return d;
}
__device__ __forceinline__ ull mul2(ull a, ull b) {
    ull d; asm("mul.rn.f32x2 %0,%1,%2;" : "=l"(d) : "l"(a), "l"(b)); return d;
}
__device__ __forceinline__ ull add2(ull a, ull b) {
    ull d; asm("add.rn.f32x2 %0,%1,%2;" : "=l"(d) : "l"(a), "l"(b)); return d;
}

// ---------------------------------------------------------------------------
// mlp_kernel v3: register-blocked GEMM. 256 threads, 128 rows/block, 250 blks
// (one full wave at 2 blocks/SM). Thread tile: 8 rows x 4 cols (L1),
// 8 rows x 8 cols (L2). X/H staged transposed + row-pair packed (stride 67).
// smem bytes: Xtp/Htp 34304 + w1s 16384 + w2s 30720 + b1s 256 = 81664
// ---------------------------------------------------------------------------
#define XSTR 67
__global__ __launch_bounds__(256, 2) void mlp_kernel(
    const float* __restrict__ X,
    const float* __restrict__ w1,
    const float* __restrict__ b1,
    const float* __restrict__ w2,
    const float* __restrict__ s_pts)
{
    extern __shared__ char smc[];
    ull*   Xtp = reinterpret_cast<ull*>(smc);                 // 64*67 = 4288 ull (reused as Htp)
    float* w1s = reinterpret_cast<float*>(smc + 34304);       // 4096
    float* w2s = reinterpret_cast<float*>(smc + 34304 + 16384); // 7680
    float* b1s = reinterpret_cast<float*>(smc + 34304 + 16384 + 30720); // 64

    const int tid  = threadIdx.x;
    const int cg   = tid & 15;
    const int rg   = tid >> 4;
    const int rg4  = rg * 4;
    const int base = blockIdx.x * 128;

    // --- prologue: repack this block's 128 s_pts rows into g_pts4 ---
    {
        float* tmp = reinterpret_cast<float*>(smc);   // overlaps Xtp, resolved by syncs
        for (int i = tid; i < 384; i += 256) tmp[i] = s_pts[base * 3 + i];
        __syncthreads();
        if (tid < 128) {
            float4 v;
            v.x = tmp[tid*3+0]; v.y = tmp[tid*3+1]; v.z = tmp[tid*3+2]; v.w = 0.f;
            g_pts4[base + tid] = v;
        }
        __syncthreads();
    }

    // --- stage weights (raw) + X transposed row-pair packed ---
    for (int i = tid; i < 4096; i += 256) w1s[i] = w1[i];
    for (int i = tid; i < 7680; i += 256) w2s[i] = w2[i];
    if (tid < 64) b1s[tid] = b1[tid];
#pragma unroll
    for (int i = 0; i < 4; i++) {
        const int idx = tid + 256 * i;
        const int c4 = idx & 15, rp = idx >> 4;   // rp 0..63
        const float4 a = *reinterpret_cast<const float4*>(X + (size_t)(base + 2*rp    ) * 64 + c4*4);
        const float4 b = *reinterpret_cast<const float4*>(X + (size_t)(base + 2*rp + 1) * 64 + c4*4);
        Xtp[(c4*4+0)*XSTR + rp] = pack2(a.x, b.x);
        Xtp[(c4*4+1)*XSTR + rp] = pack2(a.y, b.y);
        Xtp[(c4*4+2)*XSTR + rp] = pack2(a.z, b.z);
        Xtp[(c4*4+3)*XSTR + rp] = pack2(a.w, b.w);
    }
    __syncthreads();

    // --- layer 1: acc[p][q] = rows (rg*8+2p, +1), col j0+q ---
    const int j0 = cg * 4;
    ull acc[4][4];
#pragma unroll
    for (int p = 0; p < 4; p++)
#pragma unroll
        for (int q = 0; q < 4; q++) acc[p][q] = 0ull;

#pragma unroll 4
    for (int c = 0; c < 64; c++) {
        ull xp[4];
#pragma unroll
        for (int p = 0; p < 4; p++) xp[p] = Xtp[c*XSTR + rg4 + p];
        const float4 wv = *reinterpret_cast<const float4*>(&w1s[c*64 + j0]);
        const ull wd0 = pack2(wv.x, wv.x), wd1 = pack2(wv.y, wv.y);
        const ull wd2 = pack2(wv.z, wv.z), wd3 = pack2(wv.w, wv.w);
#pragma unroll
        for (int p = 0; p < 4; p++) {
            acc[p][0] = fma2(xp[p], wd0, acc[p][0]);
            acc[p][1] = fma2(xp[p], wd1, acc[p][1]);
            acc[p][2] = fma2(xp[p], wd2, acc[p][2]);
            acc[p][3] = fma2(xp[p], wd3, acc[p][3]);
        }
    }
    __syncthreads();   // all reads of Xtp done before overwriting as Htp

    // bias + leaky, store row-pair packed H
#pragma unroll
    for (int q = 0; q < 4; q++) {
        const float bq = b1s[j0 + q];
#pragma unroll
        for (int p = 0; p < 4; p++) {
            float lo, hi; unpack2(acc[p][q], lo, hi);
            lo += bq; hi += bq;
            lo = (lo >= 0.f) ? lo : 0.1f * lo;
            hi = (hi >= 0.f) ? hi : 0.1f * hi;
            Xtp[(j0 + q)*XSTR + rg4 + p] = pack2(lo, hi);   // Htp
        }
    }
    __syncthreads();

    // --- layer 2: 8 rows x 8 cols per thread, cg < 15 active ---
    if (cg < 15) {
        const int o0 = cg * 8;
        ull a2[4][8];
#pragma unroll
        for (int p = 0; p < 4; p++)
#pragma unroll
            for (int q = 0; q < 8; q++) a2[p][q] = 0ull;

#pragma unroll 2
        for (int j = 0; j < 64; j++) {
            ull xp[4];
#pragma unroll
            for (int p = 0; p < 4; p++) xp[p] = Xtp[j*XSTR + rg4 + p];
            const float4 wa = *reinterpret_cast<const float4*>(&w2s[j*120 + o0]);
            const float4 wb = *reinterpret_cast<const float4*>(&w2s[j*120 + o0 + 4]);
            const ull wd[8] = { pack2(wa.x,wa.x), pack2(wa.y,wa.y), pack2(wa.z,wa.z), pack2(wa.w,wa.w),
                                pack2(wb.x,wb.x), pack2(wb.y,wb.y), pack2(wb.z,wb.z), pack2(wb.w,wb.w) };
#pragma unroll
            for (int p = 0; p < 4; p++)
#pragma unroll
                for (int q = 0; q < 8; q++)
                    a2[p][q] = fma2(xp[p], wd[q], a2[p][q]);
        }

        // sigmoid + store both rows of each pair
#pragma unroll
        for (int p = 0; p < 4; p++) {
            const int r0 = base + rg*8 + 2*p;
            float s0[8], s1[8];
#pragma unroll
            for (int q = 0; q < 8; q++) {
                float lo, hi; unpack2(a2[p][q], lo, hi);
                s0[q] = 1.f / (1.f + __expf(-lo));
                s1[q] = 1.f / (1.f + __expf(-hi));
            }
            ull* r0p = reinterpret_cast<ull*>(g_mod + (size_t)r0 * 120 + o0);
            ull* r1p = reinterpret_cast<ull*>(g_mod + (size_t)(r0+1) * 120 + o0);
#pragma unroll
            for (int t = 0; t < 4; t++) {
                r0p[t] = pack2(s0[2*t], s0[2*t+1]);
                r1p[t] = pack2(s1[2*t], s1[2*t+1]);
            }
        }
    }
}

// ---------------------------------------------------------------------------
// kp_kernel: fused geometry + gather-weighted reduction (round-4, 39us known).
// ---------------------------------------------------------------------------
__global__ __launch_bounds__(256) void kp_kernel(
    const float* __restrict__ q_pts,
    const float* __restrict__ s_feats,
    const int*   __restrict__ nidx,
    const float* __restrict__ kpts,
    const float* __restrict__ Wg,
    float* __restrict__ out)
{
    __shared__ float sW[15 * 72];    // padded stride 72
    __shared__ float skp[45];
    __shared__ float smod[8][120];

    const int tid  = threadIdx.x;
    const int wid  = tid >> 5;
    const int lane = tid & 31;
    const int m    = blockIdx.x * 8 + wid;
    const unsigned FULL = 0xffffffffu;

    for (int i = tid; i < 960; i += 256) sW[(i >> 6) * 72 + (i & 63)] = Wg[i];
    if (tid < 45) skp[tid] = kpts[tid];
    for (int i = lane; i < 120; i += 32) smod[wid][i] = g_mod[(size_t)m * 120 + i];
    __syncthreads();

    // geometry: one neighbor per lane
    const int ind = nidx[m * HN + lane];
    const float qx = q_pts[m*3+0], qy = q_pts[m*3+1], qz = q_pts[m*3+2];
    float4 p = g_pts4[ind];
    const float nx = p.x - qx, ny = p.y - qy, nz = p.z - qz;
    float best = 3.4e38f; int bk = 0;
#pragma unroll
    for (int k = 0; k < 15; k++) {
        float dx = nx - skp[k*3+0];
        float dy = ny - skp[k*3+1];
        float dz = nz - skp[k*3+2];
        float d2 = fmaf(dx, dx, fmaf(dy, dy, dz*dz));
        if (d2 < best) { best = d2; bk = k; }   // strict <: first-min like argmin
    }
    const float infl = fmaxf(0.f, 1.f - sqrtf(best));
    const int pk = (bk << 26) | (ind << 6);

    // accumulation: half-warp g handles neighbors 2t+g; lane owns 4 channels
    const int g  = lane >> 4;
    const int cl = (lane & 15) << 2;
    ull acc0 = 0, acc1 = 0;
#pragma unroll
    for (int t = 0; t < 16; t++) {
        const int   h   = 2 * t + g;
        const int   pkh = __shfl_sync(FULL, pk,   h);
        const float s   = __shfl_sync(FULL, infl, h);
        const int   k   = pkh >> 26;
        const int   row = pkh & 0x03FFFFFF;
        const ulonglong2 f = *reinterpret_cast<const ulonglong2*>(s_feats + row + cl);
        const ulonglong2 w = *reinterpret_cast<const ulonglong2*>(&sW[k * 72 + cl]);
        const float sc = smod[wid][(k << 3) + (cl >> 3)] * s;
        const ull scp = pack2(sc, sc);
        acc0 = fma2(f.x, mul2(w.x, scp), acc0);
        acc1 = fma2(f.y, mul2(w.y, scp), acc1);
    }
    acc0 = add2(acc0, __shfl_xor_sync(FULL, acc0, 16));
    acc1 = add2(acc1, __shfl_xor_sync(FULL, acc1, 16));
    if (g == 0) {
        ulonglong2 v; v.x = acc0; v.y = acc1;
        *reinterpret_cast<ulonglong2*>(out + (size_t)m * 64 + cl) = v;
    }
}

// ---------------------------------------------------------------------------
extern "C" void kernel_launch(void* const* d_in, const int* in_sizes, int n_in,
                              void* d_out, int out_size)
{
    const float* q_pts   = (const float*)d_in[0];
    const float* s_pts   = (const float*)d_in[1];
    const float* s_feats = (const float*)d_in[2];
    const int*   nidx    = (const int*)  d_in[3];
    const float* kpts    = (const float*)d_in[4];
    const float* W       = (const float*)d_in[5];
    const float* w1      = (const float*)d_in[6];
    const float* b1      = (const float*)d_in[7];
    const float* w2      = (const float*)d_in[8];
    float* out = (float*)d_out;

    const int smem = 81664;
    static bool init = false;
    if (!init) {
        cudaFuncSetAttribute(mlp_kernel, cudaFuncAttributeMaxDynamicSharedMemorySize, smem);
        init = true;
    }

    mlp_kernel<<<250, 256, smem>>>(s_feats, w1, b1, w2, s_pts);
    kp_kernel<<<MQ / 8, 256>>>(q_pts, s_feats, nidx, kpts, W, out);
}

// round 7
// speedup vs baseline: 1.2041x; 1.0291x over previous
#include <cuda_runtime.h>
#include <cstdint>

#define MQ   32000
#define HN   32
#define CC   64
#define KK   15
#define COUTN 120

typedef unsigned long long ull;

// scratch
__device__ float  g_mod[(size_t)MQ * COUTN];   // sigmoid(mod), (M,120)
__device__ float4 g_pts4[MQ];                   // padded s_pts

// ---------------- f32x2 packed helpers (sm_103a) ----------------
__device__ __forceinline__ ull pack2(float a, float b) {
    ull r; asm("mov.b64 %0,{%1,%2};" : "=l"(r) : "f"(a), "f"(b)); return r;
}
__device__ __forceinline__ void unpack2(ull v, float& a, float& b) {
    asm("mov.b64 {%0,%1},%2;" : "=f"(a), "=f"(b) : "l"(v));
}
__device__ __forceinline__ ull fma2(ull a, ull b, ull c) {
    ull d; asm("fma.rn.f32x2 %0,%1,%2,%3;" : "=l"(d) : "l"(a), "l"(b), "l"(c)); return d;
}
__device__ __forceinline__ ull mul2(ull a, ull b) {
    ull d; asm("mul.rn.f32x2 %0,%1,%2;" : "=l"(d) : "l"(a), "l"(b)); return d;
}
__device__ __forceinline__ ull add2(ull a, ull b) {
    ull d; asm("add.rn.f32x2 %0,%1,%2;" : "=l"(d) : "l"(a), "l"(b)); return d;
}

// ---------------------------------------------------------------------------
// mlp_kernel v3 (unchanged): register-blocked GEMM + fused s_pts repack.
// smem bytes: Xtp/Htp 34304 + w1s 16384 + w2s 30720 + b1s 256 = 81664
// ---------------------------------------------------------------------------
#define XSTR 67
__global__ __launch_bounds__(256, 2) void mlp_kernel(
    const float* __restrict__ X,
    const float* __restrict__ w1,
    const float* __restrict__ b1,
    const float* __restrict__ w2,
    const float* __restrict__ s_pts)
{
    extern __shared__ char smc[];
    ull*   Xtp = reinterpret_cast<ull*>(smc);
    float* w1s = reinterpret_cast<float*>(smc + 34304);
    float* w2s = reinterpret_cast<float*>(smc + 34304 + 16384);
    float* b1s = reinterpret_cast<float*>(smc + 34304 + 16384 + 30720);

    const int tid  = threadIdx.x;
    const int cg   = tid & 15;
    const int rg   = tid >> 4;
    const int rg4  = rg * 4;
    const int base = blockIdx.x * 128;

    // prologue: repack this block's 128 s_pts rows into g_pts4
    {
        float* tmp = reinterpret_cast<float*>(smc);
        for (int i = tid; i < 384; i += 256) tmp[i] = s_pts[base * 3 + i];
        __syncthreads();
        if (tid < 128) {
            float4 v;
            v.x = tmp[tid*3+0]; v.y = tmp[tid*3+1]; v.z = tmp[tid*3+2]; v.w = 0.f;
            g_pts4[base + tid] = v;
        }
        __syncthreads();
    }

    for (int i = tid; i < 4096; i += 256) w1s[i] = w1[i];
    for (int i = tid; i < 7680; i += 256) w2s[i] = w2[i];
    if (tid < 64) b1s[tid] = b1[tid];
#pragma unroll
    for (int i = 0; i < 4; i++) {
        const int idx = tid + 256 * i;
        const int c4 = idx & 15, rp = idx >> 4;
        const float4 a = *reinterpret_cast<const float4*>(X + (size_t)(base + 2*rp    ) * 64 + c4*4);
        const float4 b = *reinterpret_cast<const float4*>(X + (size_t)(base + 2*rp + 1) * 64 + c4*4);
        Xtp[(c4*4+0)*XSTR + rp] = pack2(a.x, b.x);
        Xtp[(c4*4+1)*XSTR + rp] = pack2(a.y, b.y);
        Xtp[(c4*4+2)*XSTR + rp] = pack2(a.z, b.z);
        Xtp[(c4*4+3)*XSTR + rp] = pack2(a.w, b.w);
    }
    __syncthreads();

    const int j0 = cg * 4;
    ull acc[4][4];
#pragma unroll
    for (int p = 0; p < 4; p++)
#pragma unroll
        for (int q = 0; q < 4; q++) acc[p][q] = 0ull;

#pragma unroll 4
    for (int c = 0; c < 64; c++) {
        ull xp[4];
#pragma unroll
        for (int p = 0; p < 4; p++) xp[p] = Xtp[c*XSTR + rg4 + p];
        const float4 wv = *reinterpret_cast<const float4*>(&w1s[c*64 + j0]);
        const ull wd0 = pack2(wv.x, wv.x), wd1 = pack2(wv.y, wv.y);
        const ull wd2 = pack2(wv.z, wv.z), wd3 = pack2(wv.w, wv.w);
#pragma unroll
        for (int p = 0; p < 4; p++) {
            acc[p][0] = fma2(xp[p], wd0, acc[p][0]);
            acc[p][1] = fma2(xp[p], wd1, acc[p][1]);
            acc[p][2] = fma2(xp[p], wd2, acc[p][2]);
            acc[p][3] = fma2(xp[p], wd3, acc[p][3]);
        }
    }
    __syncthreads();

#pragma unroll
    for (int q = 0; q < 4; q++) {
        const float bq = b1s[j0 + q];
#pragma unroll
        for (int p = 0; p < 4; p++) {
            float lo, hi; unpack2(acc[p][q], lo, hi);
            lo += bq; hi += bq;
            lo = (lo >= 0.f) ? lo : 0.1f * lo;
            hi = (hi >= 0.f) ? hi : 0.1f * hi;
            Xtp[(j0 + q)*XSTR + rg4 + p] = pack2(lo, hi);
        }
    }
    __syncthreads();

    if (cg < 15) {
        const int o0 = cg * 8;
        ull a2[4][8];
#pragma unroll
        for (int p = 0; p < 4; p++)
#pragma unroll
            for (int q = 0; q < 8; q++) a2[p][q] = 0ull;

#pragma unroll 2
        for (int j = 0; j < 64; j++) {
            ull xp[4];
#pragma unroll
            for (int p = 0; p < 4; p++) xp[p] = Xtp[j*XSTR + rg4 + p];
            const float4 wa = *reinterpret_cast<const float4*>(&w2s[j*120 + o0]);
            const float4 wb = *reinterpret_cast<const float4*>(&w2s[j*120 + o0 + 4]);
            const ull wd[8] = { pack2(wa.x,wa.x), pack2(wa.y,wa.y), pack2(wa.z,wa.z), pack2(wa.w,wa.w),
                                pack2(wb.x,wb.x), pack2(wb.y,wb.y), pack2(wb.z,wb.z), pack2(wb.w,wb.w) };
#pragma unroll
            for (int p = 0; p < 4; p++)
#pragma unroll
                for (int q = 0; q < 8; q++)
                    a2[p][q] = fma2(xp[p], wd[q], a2[p][q]);
        }

#pragma unroll
        for (int p = 0; p < 4; p++) {
            const int r0 = base + rg*8 + 2*p;
            float s0[8], s1[8];
#pragma unroll
            for (int q = 0; q < 8; q++) {
                float lo, hi; unpack2(a2[p][q], lo, hi);
                s0[q] = 1.f / (1.f + __expf(-lo));
                s1[q] = 1.f / (1.f + __expf(-hi));
            }
            ull* r0p = reinterpret_cast<ull*>(g_mod + (size_t)r0 * 120 + o0);
            ull* r1p = reinterpret_cast<ull*>(g_mod + (size_t)(r0+1) * 120 + o0);
#pragma unroll
            for (int t = 0; t < 4; t++) {
                r0p[t] = pack2(s0[2*t], s0[2*t+1]);
                r1p[t] = pack2(s1[2*t], s1[2*t+1]);
            }
        }
    }
}

// ---------------------------------------------------------------------------
// kp_kernel v2: fused geometry + gather, inner loop batched x4 so the
// gather LDG.128s overlap (MLP_eff ~4-8 instead of ~2). Geo results staged
// through shared (no shfl in the hot loop).
// ---------------------------------------------------------------------------
__global__ __launch_bounds__(256) void kp_kernel(
    const float* __restrict__ q_pts,
    const float* __restrict__ s_feats,
    const int*   __restrict__ nidx,
    const float* __restrict__ kpts,
    const float* __restrict__ Wg,
    float* __restrict__ out)
{
    __shared__ float sW[15 * 72];    // padded stride 72
    __shared__ float skp[45];
    __shared__ float smod[8][120];
    __shared__ ull   sgeo[8][32];    // hi: infl bits, lo: (k<<26)|(ind<<6)

    const int tid  = threadIdx.x;
    const int wid  = tid >> 5;
    const int lane = tid & 31;
    const int m    = blockIdx.x * 8 + wid;
    const unsigned FULL = 0xffffffffu;

    for (int i = tid; i < 960; i += 256) sW[(i >> 6) * 72 + (i & 63)] = Wg[i];
    if (tid < 45) skp[tid] = kpts[tid];
    for (int i = lane; i < 120; i += 32) smod[wid][i] = g_mod[(size_t)m * 120 + i];

    // geometry: one neighbor per lane
    {
        const int ind = nidx[m * HN + lane];
        const float qx = q_pts[m*3+0], qy = q_pts[m*3+1], qz = q_pts[m*3+2];
        float4 p = g_pts4[ind];
        const float nx = p.x - qx, ny = p.y - qy, nz = p.z - qz;
        float best = 3.4e38f; int bk = 0;
        __syncthreads();   // skp ready (placed after point loads to overlap)
#pragma unroll
        for (int k = 0; k < 15; k++) {
            float dx = nx - skp[k*3+0];
            float dy = ny - skp[k*3+1];
            float dz = nz - skp[k*3+2];
            float d2 = fmaf(dx, dx, fmaf(dy, dy, dz*dz));
            if (d2 < best) { best = d2; bk = k; }   // strict <: first-min
        }
        const float infl = fmaxf(0.f, 1.f - sqrtf(best));
        const unsigned pk = ((unsigned)bk << 26) | ((unsigned)ind << 6);
        sgeo[wid][lane] = ((ull)__float_as_uint(infl) << 32) | pk;
    }
    __syncwarp();

    // accumulation: half-warp g handles neighbors 2t+g; lane owns 4 channels.
    // Batched x4: all loads for 4 neighbors issued before their math.
    const int g  = lane >> 4;
    const int cl = (lane & 15) << 2;
    ull acc0 = 0, acc1 = 0;
#pragma unroll
    for (int tb = 0; tb < 16; tb += 4) {
        ulonglong2 f[4], w[4];
        float sc[4];
#pragma unroll
        for (int u = 0; u < 4; u++) {
            const ull      geo = sgeo[wid][2 * (tb + u) + g];
            const float    s   = __uint_as_float((unsigned)(geo >> 32));
            const unsigned pkh = (unsigned)geo;
            const int      k   = pkh >> 26;
            const int      row = pkh & 0x03FFFFFF;
            f[u]  = *reinterpret_cast<const ulonglong2*>(s_feats + row + cl);
            w[u]  = *reinterpret_cast<const ulonglong2*>(&sW[k * 72 + cl]);
            sc[u] = smod[wid][(k << 3) + (cl >> 3)] * s;
        }
#pragma unroll
        for (int u = 0; u < 4; u++) {
            const ull scp = pack2(sc[u], sc[u]);
            acc0 = fma2(f[u].x, mul2(w[u].x, scp), acc0);
            acc1 = fma2(f[u].y, mul2(w[u].y, scp), acc1);
        }
    }
    acc0 = add2(acc0, __shfl_xor_sync(FULL, acc0, 16));
    acc1 = add2(acc1, __shfl_xor_sync(FULL, acc1, 16));
    if (g == 0) {
        ulonglong2 v; v.x = acc0; v.y = acc1;
        *reinterpret_cast<ulonglong2*>(out + (size_t)m * 64 + cl) = v;
    }
}

// ---------------------------------------------------------------------------
extern "C" void kernel_launch(void* const* d_in, const int* in_sizes, int n_in,
                              void* d_out, int out_size)
{
    const float* q_pts   = (const float*)d_in[0];
    const float* s_pts   = (const float*)d_in[1];
    const float* s_feats = (const float*)d_in[2];
    const int*   nidx    = (const int*)  d_in[3];
    const float* kpts    = (const float*)d_in[4];
    const float* W       = (const float*)d_in[5];
    const float* w1      = (const float*)d_in[6];
    const float* b1      = (const float*)d_in[7];
    const float* w2      = (const float*)d_in[8];
    float* out = (float*)d_out;

    const int smem = 81664;
    static bool init = false;
    if (!init) {
        cudaFuncSetAttribute(mlp_kernel, cudaFuncAttributeMaxDynamicSharedMemorySize, smem);
        init = true;
    }

    mlp_kernel<<<250, 256, smem>>>(s_feats, w1, b1, w2, s_pts);
    kp_kernel<<<MQ / 8, 256>>>(q_pts, s_feats, nidx, kpts, W, out);
}

// round 8
// speedup vs baseline: 1.5100x; 1.2541x over previous
#include <cuda_runtime.h>
#include <cstdint>

#define MQ   32000
#define HN   32
#define CC   64
#define KK   15
#define COUTN 120

typedef unsigned long long ull;

// scratch
__device__ float  g_mod[(size_t)MQ * COUTN];   // sigmoid(mod), (M,120)
__device__ float4 g_pts4[MQ];                   // padded s_pts

// ---------------- f32x2 packed helpers (sm_103a) ----------------
__device__ __forceinline__ ull pack2(float a, float b) {
    ull r; asm("mov.b64 %0,{%1,%2};" : "=l"(r) : "f"(a), "f"(b)); return r;
}
__device__ __forceinline__ void unpack2(ull v, float& a, float& b) {
    asm("mov.b64 {%0,%1},%2;" : "=f"(a), "=f"(b) : "l"(v));
}
__device__ __forceinline__ ull fma2(ull a, ull b, ull c) {
    ull d; asm("fma.rn.f32x2 %0,%1,%2,%3;" : "=l"(d) : "l"(a), "l"(b), "l"(c)); return d;
}
__device__ __forceinline__ ull mul2(ull a, ull b) {
    ull d; asm("mul.rn.f32x2 %0,%1,%2;" : "=l"(d) : "l"(a), "l"(b)); return d;
}

// ---------------------------------------------------------------------------
// mlp_kernel v3 (unchanged): register-blocked GEMM + fused s_pts repack.
// smem bytes: Xtp/Htp 34304 + w1s 16384 + w2s 30720 + b1s 256 = 81664
// ---------------------------------------------------------------------------
#define XSTR 67
__global__ __launch_bounds__(256, 2) void mlp_kernel(
    const float* __restrict__ X,
    const float* __restrict__ w1,
    const float* __restrict__ b1,
    const float* __restrict__ w2,
    const float* __restrict__ s_pts)
{
    extern __shared__ char smc[];
    ull*   Xtp = reinterpret_cast<ull*>(smc);
    float* w1s = reinterpret_cast<float*>(smc + 34304);
    float* w2s = reinterpret_cast<float*>(smc + 34304 + 16384);
    float* b1s = reinterpret_cast<float*>(smc + 34304 + 16384 + 30720);

    const int tid  = threadIdx.x;
    const int cg   = tid & 15;
    const int rg   = tid >> 4;
    const int rg4  = rg * 4;
    const int base = blockIdx.x * 128;

    // prologue: repack this block's 128 s_pts rows into g_pts4
    {
        float* tmp = reinterpret_cast<float*>(smc);
        for (int i = tid; i < 384; i += 256) tmp[i] = s_pts[base * 3 + i];
        __syncthreads();
        if (tid < 128) {
            float4 v;
            v.x = tmp[tid*3+0]; v.y = tmp[tid*3+1]; v.z = tmp[tid*3+2]; v.w = 0.f;
            g_pts4[base + tid] = v;
        }
        __syncthreads();
    }

    for (int i = tid; i < 4096; i += 256) w1s[i] = w1[i];
    for (int i = tid; i < 7680; i += 256) w2s[i] = w2[i];
    if (tid < 64) b1s[tid] = b1[tid];
#pragma unroll
    for (int i = 0; i < 4; i++) {
        const int idx = tid + 256 * i;
        const int c4 = idx & 15, rp = idx >> 4;
        const float4 a = *reinterpret_cast<const float4*>(X + (size_t)(base + 2*rp    ) * 64 + c4*4);
        const float4 b = *reinterpret_cast<const float4*>(X + (size_t)(base + 2*rp + 1) * 64 + c4*4);
        Xtp[(c4*4+0)*XSTR + rp] = pack2(a.x, b.x);
        Xtp[(c4*4+1)*XSTR + rp] = pack2(a.y, b.y);
        Xtp[(c4*4+2)*XSTR + rp] = pack2(a.z, b.z);
        Xtp[(c4*4+3)*XSTR + rp] = pack2(a.w, b.w);
    }
    __syncthreads();

    const int j0 = cg * 4;
    ull acc[4][4];
#pragma unroll
    for (int p = 0; p < 4; p++)
#pragma unroll
        for (int q = 0; q < 4; q++) acc[p][q] = 0ull;

#pragma unroll 4
    for (int c = 0; c < 64; c++) {
        ull xp[4];
#pragma unroll
        for (int p = 0; p < 4; p++) xp[p] = Xtp[c*XSTR + rg4 + p];
        const float4 wv = *reinterpret_cast<const float4*>(&w1s[c*64 + j0]);
        const ull wd0 = pack2(wv.x, wv.x), wd1 = pack2(wv.y, wv.y);
        const ull wd2 = pack2(wv.z, wv.z), wd3 = pack2(wv.w, wv.w);
#pragma unroll
        for (int p = 0; p < 4; p++) {
            acc[p][0] = fma2(xp[p], wd0, acc[p][0]);
            acc[p][1] = fma2(xp[p], wd1, acc[p][1]);
            acc[p][2] = fma2(xp[p], wd2, acc[p][2]);
            acc[p][3] = fma2(xp[p], wd3, acc[p][3]);
        }
    }
    __syncthreads();

#pragma unroll
    for (int q = 0; q < 4; q++) {
        const float bq = b1s[j0 + q];
#pragma unroll
        for (int p = 0; p < 4; p++) {
            float lo, hi; unpack2(acc[p][q], lo, hi);
            lo += bq; hi += bq;
            lo = (lo >= 0.f) ? lo : 0.1f * lo;
            hi = (hi >= 0.f) ? hi : 0.1f * hi;
            Xtp[(j0 + q)*XSTR + rg4 + p] = pack2(lo, hi);
        }
    }
    __syncthreads();

    if (cg < 15) {
        const int o0 = cg * 8;
        ull a2[4][8];
#pragma unroll
        for (int p = 0; p < 4; p++)
#pragma unroll
            for (int q = 0; q < 8; q++) a2[p][q] = 0ull;

#pragma unroll 2
        for (int j = 0; j < 64; j++) {
            ull xp[4];
#pragma unroll
            for (int p = 0; p < 4; p++) xp[p] = Xtp[j*XSTR + rg4 + p];
            const float4 wa = *reinterpret_cast<const float4*>(&w2s[j*120 + o0]);
            const float4 wb = *reinterpret_cast<const float4*>(&w2s[j*120 + o0 + 4]);
            const ull wd[8] = { pack2(wa.x,wa.x), pack2(wa.y,wa.y), pack2(wa.z,wa.z), pack2(wa.w,wa.w),
                                pack2(wb.x,wb.x), pack2(wb.y,wb.y), pack2(wb.z,wb.z), pack2(wb.w,wb.w) };
#pragma unroll
            for (int p = 0; p < 4; p++)
#pragma unroll
                for (int q = 0; q < 8; q++)
                    a2[p][q] = fma2(xp[p], wd[q], a2[p][q]);
        }

#pragma unroll
        for (int p = 0; p < 4; p++) {
            const int r0 = base + rg*8 + 2*p;
            float s0[8], s1[8];
#pragma unroll
            for (int q = 0; q < 8; q++) {
                float lo, hi; unpack2(a2[p][q], lo, hi);
                s0[q] = 1.f / (1.f + __expf(-lo));
                s1[q] = 1.f / (1.f + __expf(-hi));
            }
            ull* r0p = reinterpret_cast<ull*>(g_mod + (size_t)r0 * 120 + o0);
            ull* r1p = reinterpret_cast<ull*>(g_mod + (size_t)(r0+1) * 120 + o0);
#pragma unroll
            for (int t = 0; t < 4; t++) {
                r0p[t] = pack2(s0[2*t], s0[2*t+1]);
                r1p[t] = pack2(s1[2*t], s1[2*t+1]);
            }
        }
    }
}

// ---------------------------------------------------------------------------
// kp_kernel v3: fused geometry + SPARSE gather. Neighbors with zero linear
// influence (nn distance >= 1) contribute exactly 0 and are skipped via a
// warp ballot. Full warp per active neighbor; lane owns 2 channels.
// ---------------------------------------------------------------------------
__global__ __launch_bounds__(256) void kp_kernel(
    const float* __restrict__ q_pts,
    const float* __restrict__ s_feats,
    const int*   __restrict__ nidx,
    const float* __restrict__ kpts,
    const float* __restrict__ Wg,
    float* __restrict__ out)
{
    __shared__ float sW[15 * 72];    // padded stride 72
    __shared__ float skp[45];
    __shared__ float smod[8][120];

    const int tid  = threadIdx.x;
    const int wid  = tid >> 5;
    const int lane = tid & 31;
    const int m    = blockIdx.x * 8 + wid;
    const unsigned FULL = 0xffffffffu;

    for (int i = tid; i < 960; i += 256) sW[(i >> 6) * 72 + (i & 63)] = Wg[i];
    if (tid < 45) skp[tid] = kpts[tid];
    for (int i = lane; i < 120; i += 32) smod[wid][i] = g_mod[(size_t)m * 120 + i];

    // geometry: one neighbor per lane
    const int ind = nidx[m * HN + lane];
    const float qx = q_pts[m*3+0], qy = q_pts[m*3+1], qz = q_pts[m*3+2];
    float4 p = g_pts4[ind];
    const float nx = p.x - qx, ny = p.y - qy, nz = p.z - qz;
    float best = 3.4e38f; int bk = 0;
    __syncthreads();   // skp/sW/smod ready
#pragma unroll
    for (int k = 0; k < 15; k++) {
        float dx = nx - skp[k*3+0];
        float dy = ny - skp[k*3+1];
        float dz = nz - skp[k*3+2];
        float d2 = fmaf(dx, dx, fmaf(dy, dy, dz*dz));
        if (d2 < best) { best = d2; bk = k; }   // strict <: first-min like argmin
    }
    const float infl = fmaxf(0.f, 1.f - sqrtf(best));
    const unsigned pk = ((unsigned)bk << 26) | ((unsigned)ind << 6);

    // sparse accumulation: only neighbors with best < 1 (infl > 0) matter.
    unsigned mask = __ballot_sync(FULL, best < 1.0f);
    const int c2 = lane << 1;                       // this lane's 2 channels
    ull acc = 0ull;
    while (mask) {
        const int h = __ffs(mask) - 1;
        mask &= mask - 1;
        const unsigned pkh = __shfl_sync(FULL, pk,   h);
        const float    s   = __shfl_sync(FULL, infl, h);
        const int      k   = pkh >> 26;
        const int      row = pkh & 0x03FFFFFF;
        const ull f = *reinterpret_cast<const ull*>(s_feats + row + c2);
        const ull w = *reinterpret_cast<const ull*>(&sW[k * 72 + c2]);
        const float sc = smod[wid][(k << 3) + (lane >> 2)] * s;
        acc = fma2(f, mul2(w, pack2(sc, sc)), acc);
    }
    *reinterpret_cast<ull*>(out + (size_t)m * 64 + c2) = acc;
}

// ---------------------------------------------------------------------------
extern "C" void kernel_launch(void* const* d_in, const int* in_sizes, int n_in,
                              void* d_out, int out_size)
{
    const float* q_pts   = (const float*)d_in[0];
    const float* s_pts   = (const float*)d_in[1];
    const float* s_feats = (const float*)d_in[2];
    const int*   nidx    = (const int*)  d_in[3];
    const float* kpts    = (const float*)d_in[4];
    const float* W       = (const float*)d_in[5];
    const float* w1      = (const float*)d_in[6];
    const float* b1      = (const float*)d_in[7];
    const float* w2      = (const float*)d_in[8];
    float* out = (float*)d_out;

    const int smem = 81664;
    static bool init = false;
    if (!init) {
        cudaFuncSetAttribute(mlp_kernel, cudaFuncAttributeMaxDynamicSharedMemorySize, smem);
        init = true;
    }

    mlp_kernel<<<250, 256, smem>>>(s_feats, w1, b1, w2, s_pts);
    kp_kernel<<<MQ / 8, 256>>>(q_pts, s_feats, nidx, kpts, W, out);
}